// round 12
// baseline (speedup 1.0000x reference)
#include <cuda_runtime.h>
#include <cuda_bf16.h>
#include <cstdint>

#define Hc 4
#define Bc 4
#define Nc 2048
#define Fc 128
#define Uc 64
#define NW (Nc/32)           // 64 words per adjacency row
#define TJ 256               // j-tile staged in smem (double-buffered)
#define TJP 264              // padded row stride (halves): conflict-free ldmatrix
#define BUFH (Uc*TJP)        // halves per buffer (16896)
#define NTILE (Nc/TJ)        // 8 tiles

#define SMEM_MAIN (Nc*4 + 2*BUFH*2)   // 8192 + 67584 = 75776 -> 2 blocks/SM

// Scratch (device globals; no dynamic allocation allowed)
__device__ float g_s[Hc*Bc*Nc];                                      // 128 KB
__device__ __align__(16) __nv_bfloat16 g_projT[(size_t)Hc*Bc*Uc*Nc]; // 4 MB, [h][b][u][n]
__device__ unsigned g_bits[(size_t)Bc*Nc*NW];                        // 2 MB

__device__ __forceinline__ float ex2f(float x){
  float y; asm("ex2.approx.f32 %0, %1;" : "=f"(y) : "f"(x)); return y;
}

// ---------------------------------------------------------------------------
// ONE prep kernel, FINE-GRAINED INTERLEAVE: every 19th block is a proj block,
// the rest are zero/pack blocks. Keeps a proj+pack mix resident on every SM
// for the whole kernel so DRAM streaming hides under proj FFMA.
#define RB 32
#define PROJB ((Nc/RB)*Bc)                 // 256 proj blocks
#define ZBLK4 ((Bc*Nc*Uc/4)/256)           // 512 zero blocks (float4)
#define PBLK4 ((Bc*Nc*Nc)/(16*256))        // 4096 pack blocks (4 x uint4 / thread)
#define PREPG (PROJB + ZBLK4 + PBLK4)      // 4864 = 256*19

__global__ __launch_bounds__(256) void k_prep(
    const float* __restrict__ x, const float* __restrict__ W,
    const float* __restrict__ bias, const float* __restrict__ aw,
    const float* __restrict__ ab, const int* __restrict__ adj,
    float* __restrict__ out){
  __shared__ float xs[RB*Fc];        // 16 KB
  __shared__ float ws[32*256];       // 32 KB
  unsigned bid = blockIdx.x;
  int tid = threadIdx.x;
  unsigned pjb = bid / 19u;

  if (bid % 19u != 0u){
    unsigned r = bid - pjb - 1u;     // non-proj index 0..4607
    if (r < ZBLK4){
      ((float4*)out)[(size_t)r*256 + tid] = make_float4(0.f,0.f,0.f,0.f);
      return;
    }
    // ---- pack path: 1024 uint4 (4096 adj elems) per block, 4 loads/thread ----
    size_t q = (size_t)(r - ZBLK4)*1024 + tid;
    uint4 v0 = ((const uint4*)adj)[q];
    uint4 v1 = ((const uint4*)adj)[q + 256];
    uint4 v2 = ((const uint4*)adj)[q + 512];
    uint4 v3 = ((const uint4*)adj)[q + 768];
    unsigned lane = tid & 31;
    unsigned sh = 4u*(lane & 7u);
    unsigned w0 = ((unsigned)(v0.x>0) | ((unsigned)(v0.y>0)<<1)
                | ((unsigned)(v0.z>0)<<2) | ((unsigned)(v0.w>0)<<3)) << sh;
    unsigned w1 = ((unsigned)(v1.x>0) | ((unsigned)(v1.y>0)<<1)
                | ((unsigned)(v1.z>0)<<2) | ((unsigned)(v1.w>0)<<3)) << sh;
    unsigned w2 = ((unsigned)(v2.x>0) | ((unsigned)(v2.y>0)<<1)
                | ((unsigned)(v2.z>0)<<2) | ((unsigned)(v2.w>0)<<3)) << sh;
    unsigned w3 = ((unsigned)(v3.x>0) | ((unsigned)(v3.y>0)<<1)
                | ((unsigned)(v3.z>0)<<2) | ((unsigned)(v3.w>0)<<3)) << sh;
    #pragma unroll
    for (int m = 1; m <= 4; m <<= 1){
      w0 |= __shfl_xor_sync(0xffffffffu, w0, m);
      w1 |= __shfl_xor_sync(0xffffffffu, w1, m);
      w2 |= __shfl_xor_sync(0xffffffffu, w2, m);
      w3 |= __shfl_xor_sync(0xffffffffu, w3, m);
    }
    if ((lane & 7u) == 0){
      g_bits[ q        >> 3] = w0;
      g_bits[(q + 256) >> 3] = w1;
      g_bits[(q + 512) >> 3] = w2;
      g_bits[(q + 768) >> 3] = w3;
    }
    return;
  }

  // ---- proj path: relu(x@W[h]+b) all 4 heads as one 256-col GEMM ----
  int cg = tid & 63, rg = tid >> 6;
  int nt = pjb & 63;
  int b  = pjb >> 6;
  int n0 = nt * RB;
  int h  = cg >> 4;
  int u0 = (cg & 15) * 4;

  const float4* xp = (const float4*)(x + ((size_t)b*Nc + n0)*Fc);
  #pragma unroll
  for (int i = 0; i < 4; i++) ((float4*)xs)[tid + i*256] = xp[tid + i*256];

  float4 bv = *(const float4*)&bias[h*Uc + u0];
  float acc[8][4];
  #pragma unroll
  for (int r = 0; r < 8; r++){
    acc[r][0]=bv.x; acc[r][1]=bv.y; acc[r][2]=bv.z; acc[r][3]=bv.w;
  }

  for (int kc = 0; kc < 4; kc++){
    int f0 = kc*32;
    __syncthreads();
    #pragma unroll
    for (int i = 0; i < 8; i++){
      int idx4 = tid + i*256;
      int fr = idx4 >> 6, cq = idx4 & 63;
      ((float4*)ws)[idx4] =
        *(const float4*)(W + (size_t)(cq>>4)*Fc*Uc + (size_t)(f0+fr)*Uc + (cq&15)*4);
    }
    __syncthreads();
    #pragma unroll 4
    for (int f = 0; f < 32; f++){
      float4 wv = ((const float4*)ws)[f*64 + cg];
      float xv[8];
      #pragma unroll
      for (int r = 0; r < 8; r++) xv[r] = xs[(rg*8+r)*Fc + f0 + f];
      #pragma unroll
      for (int r = 0; r < 8; r++){
        float xr = xv[r];
        acc[r][0] += xr*wv.x; acc[r][1] += xr*wv.y;
        acc[r][2] += xr*wv.z; acc[r][3] += xr*wv.w;
      }
    }
  }

  float4 av = *(const float4*)&aw[h*Uc + u0];
  float aq[4] = {av.x, av.y, av.z, av.w};
  float sp[8];
  #pragma unroll
  for (int r = 0; r < 8; r++) sp[r] = 0.f;

  #pragma unroll
  for (int q = 0; q < 4; q++){
    __nv_bfloat16 tmp[8];
    #pragma unroll
    for (int r = 0; r < 8; r++){
      float v = fmaxf(acc[r][q], 0.f);
      sp[r] += v * aq[q];
      tmp[r] = __float2bfloat16(v);
    }
    *(uint4*)(g_projT + (((size_t)h*Bc + b)*Uc + (u0+q))*Nc + n0 + rg*8) = *(uint4*)tmp;
  }
  #pragma unroll
  for (int m = 1; m < 16; m <<= 1){
    #pragma unroll
    for (int r = 0; r < 8; r++) sp[r] += __shfl_xor_sync(0xffffffffu, sp[r], m);
  }
  if ((cg & 15) == 0){
    float abh = ab[h];
    #pragma unroll
    for (int r = 0; r < 8; r++)
      g_s[((size_t)h*Bc + b)*Nc + n0 + rg*8 + r] = sp[r] + abh;
  }
}

// ---------------------------------------------------------------------------
// Fused masked-exp softmax-aggregation via mma.sync bf16 + ldmatrix B-frags.
// pj tile double-buffered via cp.async: tile t+1 streams while tile t computes.
__global__ __launch_bounds__(256, 2) void k_main(float* __restrict__ out){
  extern __shared__ char smem[];
  float*         s_sh = (float*)smem;                    // Nc floats
  __nv_bfloat16* pj   = (__nv_bfloat16*)(smem + Nc*4);   // 2 x (64 x TJP) halves

  int it = blockIdx.x, b = blockIdx.y, h = blockIdx.z;
  int i0 = it * 128;
  int tid = threadIdx.x, wid = tid >> 5, lane = tid & 31;
  int g = lane >> 2, c = lane & 3;
  int sh0 = 2*c;

  const float* sg = g_s + ((size_t)h*Bc + b)*Nc;
  #pragma unroll
  for (int i = 0; i < 2; i++)
    ((float4*)s_sh)[tid + i*256] = ((const float4*)sg)[tid + i*256];

  int r0 = wid*16 + g;
  float si0l = sg[i0 + r0]     * 1.4426950408889634f;
  float si1l = sg[i0 + r0 + 8] * 1.4426950408889634f;

  const unsigned* brow0 = g_bits + ((size_t)b*Nc + i0 + r0)*NW;
  const unsigned* brow1 = brow0 + 8*NW;

  const __nv_bfloat16* ptg = g_projT + ((size_t)h*Bc + b)*Uc*Nc;
  unsigned pj_base = (unsigned)__cvta_generic_to_shared(pj);

  // stage tile t into buffer (t&1) via cp.async (8 x 16B per thread)
  int su = tid >> 5, sseg = tid & 31;                 // 64 rows x 32 segs
  unsigned sdst0 = pj_base + (unsigned)(su*TJP + sseg*8)*2u;
  const __nv_bfloat16* ssrc0 = ptg + (size_t)su*Nc + sseg*8;
  #define STAGE(t) do{                                                        \
    unsigned dst = sdst0 + ((t)&1)*(unsigned)(BUFH*2);                        \
    const __nv_bfloat16* src = ssrc0 + (t)*TJ;                                \
    _Pragma("unroll")                                                         \
    for (int i_ = 0; i_ < 8; i_++){                                           \
      asm volatile("cp.async.cg.shared.global [%0], [%1], 16;"                \
        :: "r"(dst + (unsigned)(i_*8*TJP*2)), "l"(src + (size_t)i_*8*Nc));    \
    }                                                                         \
    asm volatile("cp.async.commit_group;");                                   \
  } while(0)

  unsigned lmaddr[4];
  {
    int q = lane >> 3, i = lane & 7;
    #pragma unroll
    for (int p = 0; p < 4; p++){
      int row  = (2*p + (q>>1))*8 + i;   // u index
      int koff = (q & 1)*8;              // k halves
      lmaddr[p] = pj_base + (unsigned)(row*TJP + koff)*2u;
    }
  }

  float cacc[32];
  #pragma unroll
  for (int i = 0; i < 32; i++) cacc[i] = 0.f;
  float dz[4] = {0.f, 0.f, 0.f, 0.f};
  const unsigned ONES = 0x3F803F80u;     // bf16x2 {1.0, 1.0}

  STAGE(0);

  for (int t = 0; t < NTILE; t++){
    if (t + 1 < NTILE){
      STAGE(t+1);
      asm volatile("cp.async.wait_group 1;");
    } else {
      asm volatile("cp.async.wait_group 0;");
    }
    __syncthreads();                     // tile t visible to all warps
    unsigned bufoff = (unsigned)((t&1)*(BUFH*2));
    int jt = t*TJ;
    int wbase = t*8;

    #pragma unroll 1
    for (int q128 = 0; q128 < 2; q128++){
      uint4 bw0 = *(const uint4*)(brow0 + wbase + q128*4);
      uint4 bw1 = *(const uint4*)(brow1 + wbase + q128*4);
      #pragma unroll
      for (int w = 0; w < 4; w++){
        unsigned wr0 = (w==0)?bw0.x:(w==1)?bw0.y:(w==2)?bw0.z:bw0.w;
        unsigned wr1 = (w==0)?bw1.x:(w==1)?bw1.y:(w==2)?bw1.z:bw1.w;
        unsigned wrs0 = wr0 >> sh0;
        unsigned wrs1 = wr1 >> sh0;
        #pragma unroll
        for (int half = 0; half < 2; half++){
          const unsigned B0 = 1u << (half*16), B1 = 2u << (half*16);
          const unsigned B8 = 256u << (half*16), B9 = 512u << (half*16);
          int k  = q128*128 + w*32 + half*16;
          int j0 = jt + k;

          float2 sjA = *(const float2*)&s_sh[j0 + sh0];
          float2 sjB = *(const float2*)&s_sh[j0 + sh0 + 8];

          float e00 = ex2f(si0l*sjA.x), e01 = ex2f(si0l*sjA.y);
          float e02 = ex2f(si0l*sjB.x), e03 = ex2f(si0l*sjB.y);
          float e10 = ex2f(si1l*sjA.x), e11 = ex2f(si1l*sjA.y);
          float e12 = ex2f(si1l*sjB.x), e13 = ex2f(si1l*sjB.y);

          if (!(wrs0 & B0)) e00 = 0.f;
          if (!(wrs0 & B1)) e01 = 0.f;
          if (!(wrs0 & B8)) e02 = 0.f;
          if (!(wrs0 & B9)) e03 = 0.f;
          if (!(wrs1 & B0)) e10 = 0.f;
          if (!(wrs1 & B1)) e11 = 0.f;
          if (!(wrs1 & B8)) e12 = 0.f;
          if (!(wrs1 & B9)) e13 = 0.f;

          unsigned a0,a1,a2,a3;
          { __nv_bfloat162 tt = __floats2bfloat162_rn(e00,e01); a0 = *(unsigned*)&tt; }
          { __nv_bfloat162 tt = __floats2bfloat162_rn(e10,e11); a1 = *(unsigned*)&tt; }
          { __nv_bfloat162 tt = __floats2bfloat162_rn(e02,e03); a2 = *(unsigned*)&tt; }
          { __nv_bfloat162 tt = __floats2bfloat162_rn(e12,e13); a3 = *(unsigned*)&tt; }

          unsigned bf[4][4];
          #pragma unroll
          for (int p = 0; p < 4; p++){
            asm volatile("ldmatrix.sync.aligned.m8n8.x4.shared.b16 {%0,%1,%2,%3}, [%4];"
              : "=r"(bf[p][0]), "=r"(bf[p][1]), "=r"(bf[p][2]), "=r"(bf[p][3])
              : "r"(lmaddr[p] + bufoff + (unsigned)(k*2)));
          }

          asm volatile("mma.sync.aligned.m16n8k16.row.col.f32.bf16.bf16.f32 "
            "{%0,%1,%2,%3}, {%4,%5,%6,%7}, {%8,%9}, {%0,%1,%2,%3};"
            : "+f"(dz[0]), "+f"(dz[1]), "+f"(dz[2]), "+f"(dz[3])
            : "r"(a0),"r"(a1),"r"(a2),"r"(a3), "r"(ONES), "r"(ONES));

          #pragma unroll
          for (int t8 = 0; t8 < 8; t8++){
            unsigned bb0 = bf[t8>>1][(t8&1)*2];
            unsigned bb1 = bf[t8>>1][(t8&1)*2 + 1];
            float* d = cacc + t8*4;
            asm volatile("mma.sync.aligned.m16n8k16.row.col.f32.bf16.bf16.f32 "
              "{%0,%1,%2,%3}, {%4,%5,%6,%7}, {%8,%9}, {%0,%1,%2,%3};"
              : "+f"(d[0]), "+f"(d[1]), "+f"(d[2]), "+f"(d[3])
              : "r"(a0),"r"(a1),"r"(a2),"r"(a3), "r"(bb0), "r"(bb1));
          }
        }
      }
    }
    __syncthreads();                     // buf (t&1) free before stage(t+2)
  }

  float inv0 = 1.f / (4.f * dz[0]);   // /Z and /H ; all quad lanes identical
  float inv1 = 1.f / (4.f * dz[2]);

  float* o0 = out + ((size_t)b*Nc + i0 + r0)*Uc;
  float* o1 = o0 + 8*Uc;
  #pragma unroll
  for (int t8 = 0; t8 < 8; t8++){
    int u = t8*8 + sh0;
    atomicAdd(&o0[u],   cacc[t8*4+0]*inv0);
    atomicAdd(&o0[u+1], cacc[t8*4+1]*inv0);
    atomicAdd(&o1[u],   cacc[t8*4+2]*inv1);
    atomicAdd(&o1[u+1], cacc[t8*4+3]*inv1);
  }
}

// ---------------------------------------------------------------------------
extern "C" void kernel_launch(void* const* d_in, const int* in_sizes, int n_in,
                              void* d_out, int out_size){
  const float* x    = (const float*)d_in[0];
  const int*   adj  = (const int*)d_in[1];
  const float* W    = (const float*)d_in[2];
  const float* bias = (const float*)d_in[3];
  const float* aw   = (const float*)d_in[4];
  const float* ab   = (const float*)d_in[5];
  float* out = (float*)d_out;

  cudaFuncSetAttribute(k_main, cudaFuncAttributeMaxDynamicSharedMemorySize, SMEM_MAIN);

  k_prep<<<PREPG, 256>>>(x, W, bias, aw, ab, adj, out);
  k_main<<<dim3(Nc/128, Bc, Hc), 256, SMEM_MAIN>>>(out);
}

// round 13
// speedup vs baseline: 1.0709x; 1.0709x over previous
#include <cuda_runtime.h>
#include <cuda_bf16.h>
#include <cstdint>

#define Hc 4
#define Bc 4
#define Nc 2048
#define Fc 128
#define Uc 64
#define NW (Nc/32)           // 64 words per adjacency row
#define TJ 128               // j-tile staged in smem (double-buffered)
#define TJP 136              // padded row stride (halves): conflict-free ldmatrix
#define BUFH (Uc*TJP)        // halves per buffer (8704)
#define NTILE (Nc/TJ)        // 16 tiles

#define SMEM_MAIN (Nc*4 + 2*BUFH*2)   // 8192 + 34816 = 43008 -> 3 blocks/SM (w/ 85 regs)

// Scratch (device globals; no dynamic allocation allowed)
__device__ float g_s[Hc*Bc*Nc];                                      // 128 KB
__device__ __align__(16) __nv_bfloat16 g_projT[(size_t)Hc*Bc*Uc*Nc]; // 4 MB, [h][b][u][n]
__device__ unsigned g_bits[(size_t)Bc*Nc*NW];                        // 2 MB

__device__ __forceinline__ float ex2f(float x){
  float y; asm("ex2.approx.f32 %0, %1;" : "=f"(y) : "f"(x)); return y;
}

// ---------------------------------------------------------------------------
// ONE prep kernel (round-11 layout: proj blocks first, then zero, then pack).
#define RB 32
#define PROJB ((Nc/RB)*Bc)                 // 256 proj blocks
#define ZBLK4 ((Bc*Nc*Uc/4)/256)           // 512 zero blocks (float4)
#define PBLK4 ((Bc*Nc*Nc)/(16*256))        // 4096 pack blocks (4 x uint4 / thread)

__global__ __launch_bounds__(256) void k_prep(
    const float* __restrict__ x, const float* __restrict__ W,
    const float* __restrict__ bias, const float* __restrict__ aw,
    const float* __restrict__ ab, const int* __restrict__ adj,
    float* __restrict__ out){
  __shared__ float xs[RB*Fc];        // 16 KB
  __shared__ float ws[32*256];       // 32 KB
  unsigned bid = blockIdx.x;
  int tid = threadIdx.x;

  if (bid >= PROJB){
    unsigned b2 = bid - PROJB;
    if (b2 < ZBLK4){
      ((float4*)out)[(size_t)b2*256 + tid] = make_float4(0.f,0.f,0.f,0.f);
      return;
    }
    // ---- pack path: 1024 uint4 (4096 adj elems) per block, 4 loads/thread ----
    size_t q = (size_t)(b2 - ZBLK4)*1024 + tid;
    uint4 v0 = ((const uint4*)adj)[q];
    uint4 v1 = ((const uint4*)adj)[q + 256];
    uint4 v2 = ((const uint4*)adj)[q + 512];
    uint4 v3 = ((const uint4*)adj)[q + 768];
    unsigned lane = tid & 31;
    unsigned sh = 4u*(lane & 7u);
    unsigned w0 = ((unsigned)(v0.x>0) | ((unsigned)(v0.y>0)<<1)
                | ((unsigned)(v0.z>0)<<2) | ((unsigned)(v0.w>0)<<3)) << sh;
    unsigned w1 = ((unsigned)(v1.x>0) | ((unsigned)(v1.y>0)<<1)
                | ((unsigned)(v1.z>0)<<2) | ((unsigned)(v1.w>0)<<3)) << sh;
    unsigned w2 = ((unsigned)(v2.x>0) | ((unsigned)(v2.y>0)<<1)
                | ((unsigned)(v2.z>0)<<2) | ((unsigned)(v2.w>0)<<3)) << sh;
    unsigned w3 = ((unsigned)(v3.x>0) | ((unsigned)(v3.y>0)<<1)
                | ((unsigned)(v3.z>0)<<2) | ((unsigned)(v3.w>0)<<3)) << sh;
    #pragma unroll
    for (int m = 1; m <= 4; m <<= 1){
      w0 |= __shfl_xor_sync(0xffffffffu, w0, m);
      w1 |= __shfl_xor_sync(0xffffffffu, w1, m);
      w2 |= __shfl_xor_sync(0xffffffffu, w2, m);
      w3 |= __shfl_xor_sync(0xffffffffu, w3, m);
    }
    if ((lane & 7u) == 0){
      g_bits[ q        >> 3] = w0;
      g_bits[(q + 256) >> 3] = w1;
      g_bits[(q + 512) >> 3] = w2;
      g_bits[(q + 768) >> 3] = w3;
    }
    return;
  }

  // ---- proj path: relu(x@W[h]+b) all 4 heads as one 256-col GEMM ----
  int cg = tid & 63, rg = tid >> 6;
  int nt = bid & 63;
  int b  = bid >> 6;
  int n0 = nt * RB;
  int h  = cg >> 4;
  int u0 = (cg & 15) * 4;

  const float4* xp = (const float4*)(x + ((size_t)b*Nc + n0)*Fc);
  #pragma unroll
  for (int i = 0; i < 4; i++) ((float4*)xs)[tid + i*256] = xp[tid + i*256];

  float4 bv = *(const float4*)&bias[h*Uc + u0];
  float acc[8][4];
  #pragma unroll
  for (int r = 0; r < 8; r++){
    acc[r][0]=bv.x; acc[r][1]=bv.y; acc[r][2]=bv.z; acc[r][3]=bv.w;
  }

  for (int kc = 0; kc < 4; kc++){
    int f0 = kc*32;
    __syncthreads();
    #pragma unroll
    for (int i = 0; i < 8; i++){
      int idx4 = tid + i*256;
      int fr = idx4 >> 6, cq = idx4 & 63;
      ((float4*)ws)[idx4] =
        *(const float4*)(W + (size_t)(cq>>4)*Fc*Uc + (size_t)(f0+fr)*Uc + (cq&15)*4);
    }
    __syncthreads();
    #pragma unroll 4
    for (int f = 0; f < 32; f++){
      float4 wv = ((const float4*)ws)[f*64 + cg];
      float xv[8];
      #pragma unroll
      for (int r = 0; r < 8; r++) xv[r] = xs[(rg*8+r)*Fc + f0 + f];
      #pragma unroll
      for (int r = 0; r < 8; r++){
        float xr = xv[r];
        acc[r][0] += xr*wv.x; acc[r][1] += xr*wv.y;
        acc[r][2] += xr*wv.z; acc[r][3] += xr*wv.w;
      }
    }
  }

  float4 av = *(const float4*)&aw[h*Uc + u0];
  float aq[4] = {av.x, av.y, av.z, av.w};
  float sp[8];
  #pragma unroll
  for (int r = 0; r < 8; r++) sp[r] = 0.f;

  #pragma unroll
  for (int q = 0; q < 4; q++){
    __nv_bfloat16 tmp[8];
    #pragma unroll
    for (int r = 0; r < 8; r++){
      float v = fmaxf(acc[r][q], 0.f);
      sp[r] += v * aq[q];
      tmp[r] = __float2bfloat16(v);
    }
    *(uint4*)(g_projT + (((size_t)h*Bc + b)*Uc + (u0+q))*Nc + n0 + rg*8) = *(uint4*)tmp;
  }
  #pragma unroll
  for (int m = 1; m < 16; m <<= 1){
    #pragma unroll
    for (int r = 0; r < 8; r++) sp[r] += __shfl_xor_sync(0xffffffffu, sp[r], m);
  }
  if ((cg & 15) == 0){
    float abh = ab[h];
    #pragma unroll
    for (int r = 0; r < 8; r++)
      g_s[((size_t)h*Bc + b)*Nc + n0 + rg*8 + r] = sp[r] + abh;
  }
}

// ---------------------------------------------------------------------------
// Fused masked-exp softmax-aggregation, mma.sync bf16 + ldmatrix.
// TJ=128 double-buffered cp.async; 3 blocks/SM (85-reg cap); f32x2 products.
__global__ __launch_bounds__(256, 3) void k_main(float* __restrict__ out){
  extern __shared__ char smem[];
  float*         s_sh = (float*)smem;                    // Nc floats
  __nv_bfloat16* pj   = (__nv_bfloat16*)(smem + Nc*4);   // 2 x (64 x TJP) halves

  int it = blockIdx.x, b = blockIdx.y, h = blockIdx.z;
  int i0 = it * 128;
  int tid = threadIdx.x, wid = tid >> 5, lane = tid & 31;
  int g = lane >> 2, c = lane & 3;
  int sh0 = 2*c;

  const float* sg = g_s + ((size_t)h*Bc + b)*Nc;
  #pragma unroll
  for (int i = 0; i < 2; i++)
    ((float4*)s_sh)[tid + i*256] = ((const float4*)sg)[tid + i*256];

  int r0 = wid*16 + g;
  float si0l = sg[i0 + r0]     * 1.4426950408889634f;
  float si1l = sg[i0 + r0 + 8] * 1.4426950408889634f;
  unsigned long long si02, si12;                  // packed {v,v}
  asm("mov.b64 %0, {%1, %1};" : "=l"(si02) : "f"(si0l));
  asm("mov.b64 %0, {%1, %1};" : "=l"(si12) : "f"(si1l));

  const unsigned* brow0 = g_bits + ((size_t)b*Nc + i0 + r0)*NW;
  const unsigned* brow1 = brow0 + 8*NW;

  const __nv_bfloat16* ptg = g_projT + ((size_t)h*Bc + b)*Uc*Nc;
  unsigned pj_base = (unsigned)__cvta_generic_to_shared(pj);

  // stage tile t into buffer (t&1): 64 rows x 16 segs of 16B; 4 cp.async/thread
  #define STAGE(t) do{                                                        \
    unsigned bufo_ = ((t)&1)*(unsigned)(BUFH*2);                              \
    _Pragma("unroll")                                                         \
    for (int i_ = 0; i_ < 4; i_++){                                           \
      int idx_ = tid + i_*256;                                                \
      int row_ = idx_ >> 4, seg_ = idx_ & 15;                                 \
      asm volatile("cp.async.cg.shared.global [%0], [%1], 16;"                \
        :: "r"(pj_base + bufo_ + (unsigned)(row_*TJP + seg_*8)*2u),           \
           "l"(ptg + (size_t)row_*Nc + (t)*TJ + seg_*8));                     \
    }                                                                         \
    asm volatile("cp.async.commit_group;");                                   \
  } while(0)

  unsigned lmaddr[4];
  {
    int q = lane >> 3, i = lane & 7;
    #pragma unroll
    for (int p = 0; p < 4; p++){
      int row  = (2*p + (q>>1))*8 + i;   // u index
      int koff = (q & 1)*8;              // k halves
      lmaddr[p] = pj_base + (unsigned)(row*TJP + koff)*2u;
    }
  }

  float cacc[32];
  #pragma unroll
  for (int i = 0; i < 32; i++) cacc[i] = 0.f;
  float dz[4] = {0.f, 0.f, 0.f, 0.f};
  const unsigned ONES = 0x3F803F80u;     // bf16x2 {1.0, 1.0}

  STAGE(0);

  for (int t = 0; t < NTILE; t++){
    if (t + 1 < NTILE){
      STAGE(t+1);
      asm volatile("cp.async.wait_group 1;");
    } else {
      asm volatile("cp.async.wait_group 0;");
    }
    __syncthreads();                     // tile t visible to all warps
    unsigned bufoff = (unsigned)((t&1)*(BUFH*2));
    int jt = t*TJ;

    uint4 bw0 = *(const uint4*)(brow0 + t*4);   // 128 j of row r0
    uint4 bw1 = *(const uint4*)(brow1 + t*4);   // 128 j of row r0+8
    #pragma unroll
    for (int w = 0; w < 4; w++){
      unsigned wr0 = (w==0)?bw0.x:(w==1)?bw0.y:(w==2)?bw0.z:bw0.w;
      unsigned wr1 = (w==0)?bw1.x:(w==1)?bw1.y:(w==2)?bw1.z:bw1.w;
      unsigned wrs0 = wr0 >> sh0;
      unsigned wrs1 = wr1 >> sh0;
      #pragma unroll
      for (int half = 0; half < 2; half++){
        const unsigned B0 = 1u << (half*16), B1 = 2u << (half*16);
        const unsigned B8 = 256u << (half*16), B9 = 512u << (half*16);
        int k  = w*32 + half*16;
        int j0 = jt + k;

        unsigned long long sA = *(const unsigned long long*)&s_sh[j0 + sh0];
        unsigned long long sB = *(const unsigned long long*)&s_sh[j0 + sh0 + 8];
        unsigned long long p0, p1, p2, p3;
        asm("mul.rn.f32x2 %0, %1, %2;" : "=l"(p0) : "l"(si02), "l"(sA));
        asm("mul.rn.f32x2 %0, %1, %2;" : "=l"(p1) : "l"(si02), "l"(sB));
        asm("mul.rn.f32x2 %0, %1, %2;" : "=l"(p2) : "l"(si12), "l"(sA));
        asm("mul.rn.f32x2 %0, %1, %2;" : "=l"(p3) : "l"(si12), "l"(sB));
        float x00,x01,x02,x03,x10,x11,x12,x13;
        asm("mov.b64 {%0, %1}, %2;" : "=f"(x00), "=f"(x01) : "l"(p0));
        asm("mov.b64 {%0, %1}, %2;" : "=f"(x02), "=f"(x03) : "l"(p1));
        asm("mov.b64 {%0, %1}, %2;" : "=f"(x10), "=f"(x11) : "l"(p2));
        asm("mov.b64 {%0, %1}, %2;" : "=f"(x12), "=f"(x13) : "l"(p3));

        float e00 = ex2f(x00), e01 = ex2f(x01);
        float e02 = ex2f(x02), e03 = ex2f(x03);
        float e10 = ex2f(x10), e11 = ex2f(x11);
        float e12 = ex2f(x12), e13 = ex2f(x13);

        if (!(wrs0 & B0)) e00 = 0.f;
        if (!(wrs0 & B1)) e01 = 0.f;
        if (!(wrs0 & B8)) e02 = 0.f;
        if (!(wrs0 & B9)) e03 = 0.f;
        if (!(wrs1 & B0)) e10 = 0.f;
        if (!(wrs1 & B1)) e11 = 0.f;
        if (!(wrs1 & B8)) e12 = 0.f;
        if (!(wrs1 & B9)) e13 = 0.f;

        unsigned a0,a1,a2,a3;
        { __nv_bfloat162 tt = __floats2bfloat162_rn(e00,e01); a0 = *(unsigned*)&tt; }
        { __nv_bfloat162 tt = __floats2bfloat162_rn(e10,e11); a1 = *(unsigned*)&tt; }
        { __nv_bfloat162 tt = __floats2bfloat162_rn(e02,e03); a2 = *(unsigned*)&tt; }
        { __nv_bfloat162 tt = __floats2bfloat162_rn(e12,e13); a3 = *(unsigned*)&tt; }

        unsigned bf[4][4];
        #pragma unroll
        for (int p = 0; p < 4; p++){
          asm volatile("ldmatrix.sync.aligned.m8n8.x4.shared.b16 {%0,%1,%2,%3}, [%4];"
            : "=r"(bf[p][0]), "=r"(bf[p][1]), "=r"(bf[p][2]), "=r"(bf[p][3])
            : "r"(lmaddr[p] + bufoff + (unsigned)(k*2)));
        }

        asm volatile("mma.sync.aligned.m16n8k16.row.col.f32.bf16.bf16.f32 "
          "{%0,%1,%2,%3}, {%4,%5,%6,%7}, {%8,%9}, {%0,%1,%2,%3};"
          : "+f"(dz[0]), "+f"(dz[1]), "+f"(dz[2]), "+f"(dz[3])
          : "r"(a0),"r"(a1),"r"(a2),"r"(a3), "r"(ONES), "r"(ONES));

        #pragma unroll
        for (int t8 = 0; t8 < 8; t8++){
          unsigned bb0 = bf[t8>>1][(t8&1)*2];
          unsigned bb1 = bf[t8>>1][(t8&1)*2 + 1];
          float* d = cacc + t8*4;
          asm volatile("mma.sync.aligned.m16n8k16.row.col.f32.bf16.bf16.f32 "
            "{%0,%1,%2,%3}, {%4,%5,%6,%7}, {%8,%9}, {%0,%1,%2,%3};"
            : "+f"(d[0]), "+f"(d[1]), "+f"(d[2]), "+f"(d[3])
            : "r"(a0),"r"(a1),"r"(a2),"r"(a3), "r"(bb0), "r"(bb1));
        }
      }
    }
    __syncthreads();                     // buf (t&1) free before stage(t+2)
  }

  float inv0 = 1.f / (4.f * dz[0]);   // /Z and /H ; all quad lanes identical
  float inv1 = 1.f / (4.f * dz[2]);

  float* o0 = out + ((size_t)b*Nc + i0 + r0)*Uc;
  float* o1 = o0 + 8*Uc;
  #pragma unroll
  for (int t8 = 0; t8 < 8; t8++){
    int u = t8*8 + sh0;
    atomicAdd(&o0[u],   cacc[t8*4+0]*inv0);
    atomicAdd(&o0[u+1], cacc[t8*4+1]*inv0);
    atomicAdd(&o1[u],   cacc[t8*4+2]*inv1);
    atomicAdd(&o1[u+1], cacc[t8*4+3]*inv1);
  }
}

// ---------------------------------------------------------------------------
extern "C" void kernel_launch(void* const* d_in, const int* in_sizes, int n_in,
                              void* d_out, int out_size){
  const float* x    = (const float*)d_in[0];
  const int*   adj  = (const int*)d_in[1];
  const float* W    = (const float*)d_in[2];
  const float* bias = (const float*)d_in[3];
  const float* aw   = (const float*)d_in[4];
  const float* ab   = (const float*)d_in[5];
  float* out = (float*)d_out;

  cudaFuncSetAttribute(k_main, cudaFuncAttributeMaxDynamicSharedMemorySize, SMEM_MAIN);

  k_prep<<<PROJB + ZBLK4 + PBLK4, 256>>>(x, W, bias, aw, ab, adj, out);
  k_main<<<dim3(Nc/128, Bc, Hc), 256, SMEM_MAIN>>>(out);
}